// round 7
// baseline (speedup 1.0000x reference)
#include <cuda_runtime.h>
#include <cstdint>

#define NMAX    100000
#define IN_DIM  512
#define HID     16

typedef unsigned long long ull;

// Scratch (allocation-free per harness rules): __device__ globals.
__device__ float g_xw[(size_t)NMAX * HID];   // x @ W1           [N,16]
__device__ float g_h [(size_t)NMAX * HID];   // spmm accumulator [N,16]
__device__ float g_h2[(size_t)NMAX];         // relu(h+b1) @ W2  [N]

// ---------------------------------------------------------------------------
// K0: zero the spmm-1 accumulator (3-way split so gemm1 is ncu's slot 4)
// ---------------------------------------------------------------------------
__global__ void k_zero(int off, int lim) {
    int i = off + blockIdx.x * blockDim.x + threadIdx.x;
    if (i < lim) ((float4*)g_h)[i] = make_float4(0.f, 0.f, 0.f, 0.f);
}

// ---------------------------------------------------------------------------
// K1: g_xw = x @ W1
//   Persistent 296 blocks x 8 warps. Each warp round-robins over 16-row
//   chunks; lanes = 16 rows x 2 col-halves. Warp-private 4-stage cp.async
//   pipeline over KT=16 K-tiles, continuous across chunks (never drains).
//   No block barriers in the main loop.
// ---------------------------------------------------------------------------
#define KT2     16
#define RPW2    16                        // rows per chunk
#define PADW2   20                        // floats per row in smem (bank-safe)
#define TILEF2  (RPW2 * PADW2)            // 320 floats / 1280 B per tile buf
#define STG2    4                         // pipeline stages
#define TPC     (IN_DIM / KT2)            // 32 tiles per chunk
#define GW_B    8                         // warps per block
#define GSM_B   ((IN_DIM * HID + GW_B * STG2 * TILEF2) * 4)   // 73728 B

#define GLOAD(J)                                                              \
    {                                                                         \
        int j_   = (J);                                                       \
        int kt_  = j_ & (TPC - 1);                                            \
        int ch_  = wg + (j_ >> 5) * nw;                                       \
        int rb_  = ch_ * RPW2;                                                \
        float* dst0 = sB + (j_ & (STG2 - 1)) * TILEF2;                        \
        _Pragma("unroll")                                                     \
        for (int i_ = 0; i_ < 2; ++i_) {                                      \
            int flat = i_ * 32 + lane;                                        \
            int r_ = flat >> 2, q_ = flat & 3;                                \
            unsigned d_ = (unsigned)__cvta_generic_to_shared(                 \
                dst0 + r_ * PADW2 + q_ * 4);                                  \
            int row_ = rb_ + r_;                                              \
            int valid = (row_ < n);                                           \
            const float* s_ = x + (valid ? ((size_t)row_ * IN_DIM             \
                                            + kt_ * KT2 + q_ * 4) : 0);       \
            int sz_ = valid ? 16 : 0;                                         \
            asm volatile("cp.async.cg.shared.global [%0], [%1], 16, %2;"      \
                         :: "r"(d_), "l"(s_), "r"(sz_));                      \
        }                                                                     \
        asm volatile("cp.async.commit_group;");                              \
    }

__global__ void __launch_bounds__(256) k_gemm1(
        const float* __restrict__ x,
        const float* __restrict__ W1, int n, int nw) {
    extern __shared__ float sm[];
    float* sW = sm;

    int t    = threadIdx.x;
    int w    = t >> 5;
    int lane = t & 31;
    float* sB = sm + IN_DIM * HID + w * (STG2 * TILEF2);
    int wg   = blockIdx.x * GW_B + w;

    int rlane = lane & 15;            // row within chunk
    int half  = lane >> 4;            // column half (8 cols)

    // stage full W1 (2048 float4, 8/thread) — oldest group
#pragma unroll
    for (int i = 0; i < 8; ++i) {
        unsigned d = (unsigned)__cvta_generic_to_shared(sW + (i * 256 + t) * 4);
        const float4* s = ((const float4*)W1) + i * 256 + t;
        asm volatile("cp.async.cg.shared.global [%0], [%1], 16;"
                     :: "r"(d), "l"(s));
    }
    asm volatile("cp.async.commit_group;");

    int nchunks = (n + RPW2 - 1) / RPW2;
    int myn     = (wg < nchunks) ? ((nchunks - 1 - wg) / nw + 1) : 0;
    int ntiles  = myn * TPC;          // >= 32 for every active warp here

    // prologue: 3 tiles in flight
    if (ntiles > 0) GLOAD(0);
    if (ntiles > 1) GLOAD(1);
    if (ntiles > 2) GLOAD(2);

    asm volatile("cp.async.wait_group 3;");    // W1 group complete
    __syncthreads();                           // W1 visible to all warps

    ull acc[4];
    acc[0] = acc[1] = acc[2] = acc[3] = 0ull;

#pragma unroll 1
    for (int j = 0; j < ntiles; ++j) {
        if (j + 3 < ntiles) {
            GLOAD(j + 3);
            asm volatile("cp.async.wait_group 3;");
        } else {
            int r = ntiles - 1 - j;            // tiles still possibly pending
            if      (r == 2) asm volatile("cp.async.wait_group 2;");
            else if (r == 1) asm volatile("cp.async.wait_group 1;");
            else             asm volatile("cp.async.wait_group 0;");
        }
        __syncwarp();

        int kt = j & (TPC - 1);
        const float* sx = sB + (j & (STG2 - 1)) * TILEF2 + rlane * PADW2;
        const float* sWh = sW + half * 8;

#pragma unroll
        for (int k4 = 0; k4 < KT2 / 4; ++k4) {
            float4 v = *(const float4*)(sx + k4 * 4);
            float xs[4] = {v.x, v.y, v.z, v.w};
#pragma unroll
            for (int kk = 0; kk < 4; ++kk) {
                const ulonglong2* wr = (const ulonglong2*)
                    (sWh + (kt * KT2 + k4 * 4 + kk) * HID);
                ulonglong2 wa = wr[0];
                ulonglong2 wb = wr[1];
                ull xx;
                asm("mov.b64 %0, {%1, %1};" : "=l"(xx) : "f"(xs[kk]));
                asm("fma.rn.f32x2 %0, %1, %2, %0;" : "+l"(acc[0]) : "l"(xx), "l"(wa.x));
                asm("fma.rn.f32x2 %0, %1, %2, %0;" : "+l"(acc[1]) : "l"(xx), "l"(wa.y));
                asm("fma.rn.f32x2 %0, %1, %2, %0;" : "+l"(acc[2]) : "l"(xx), "l"(wb.x));
                asm("fma.rn.f32x2 %0, %1, %2, %0;" : "+l"(acc[3]) : "l"(xx), "l"(wb.y));
            }
        }

        if (kt == TPC - 1) {                   // chunk finished: write 8 cols
            int chunk = wg + (j >> 5) * nw;
            int row   = chunk * RPW2 + rlane;
            if (row < n) {
                ulonglong2* o =
                    (ulonglong2*)(g_xw + (size_t)row * HID + half * 8);
                o[0] = make_ulonglong2(acc[0], acc[1]);
                o[1] = make_ulonglong2(acc[2], acc[3]);
            }
            acc[0] = acc[1] = acc[2] = acc[3] = 0ull;
        }
    }
}

// ---------------------------------------------------------------------------
// K2: g_h[dst] += w * g_xw[src]   (4 threads/edge, 4-edge ILP)
// ---------------------------------------------------------------------------
__global__ void k_spmm1(const int*   __restrict__ src,
                        const int*   __restrict__ dst,
                        const float* __restrict__ w, int E, int quarter) {
    int t = blockIdx.x * blockDim.x + threadIdx.x;
    int i = t >> 2;
    if (i >= quarter) return;
    int part = t & 3;

    int  e[4];  bool hv[4];
#pragma unroll
    for (int j = 0; j < 4; ++j) {
        e[j]  = i + j * quarter;
        hv[j] = (e[j] < E);
        if (!hv[j]) e[j] = 0;
    }

    int s[4], d[4]; float ww[4];
#pragma unroll
    for (int j = 0; j < 4; ++j) {
        s[j]  = __ldg(src + e[j]);
        d[j]  = __ldg(dst + e[j]);
        ww[j] = __ldg(w   + e[j]);
    }

    float4 v[4];
#pragma unroll
    for (int j = 0; j < 4; ++j)
        v[j] = __ldg(((const float4*)g_xw) + (((size_t)s[j]) << 2) + part);

#pragma unroll
    for (int j = 0; j < 4; ++j) {
        if (!hv[j]) continue;
        float* a = g_h + (((size_t)d[j]) << 4) + (part << 2);
        asm volatile("red.global.add.v4.f32 [%0], {%1, %2, %3, %4};"
                     :: "l"(a), "f"(v[j].x * ww[j]), "f"(v[j].y * ww[j]),
                        "f"(v[j].z * ww[j]), "f"(v[j].w * ww[j]) : "memory");
    }
}

// ---------------------------------------------------------------------------
// K3: g_h2 = relu(g_h + b1) @ W2 ; out init to b2
// ---------------------------------------------------------------------------
__global__ void k_layer2a(const float* __restrict__ b1,
                          const float* __restrict__ W2,
                          const float* __restrict__ b2,
                          float* __restrict__ out, int n) {
    int i = blockIdx.x * blockDim.x + threadIdx.x;
    if (i >= n) return;
    float acc = 0.f;
#pragma unroll
    for (int p = 0; p < 4; ++p) {
        float4 hv = ((const float4*)g_h)[(size_t)i * 4 + p];
        float4 bv = __ldg(((const float4*)b1) + p);
        float4 wv = __ldg(((const float4*)W2) + p);
        acc += fmaxf(hv.x + bv.x, 0.f) * wv.x
             + fmaxf(hv.y + bv.y, 0.f) * wv.y
             + fmaxf(hv.z + bv.z, 0.f) * wv.z
             + fmaxf(hv.w + bv.w, 0.f) * wv.w;
    }
    g_h2[i] = acc;
    out[i]  = __ldg(b2);
}

// ---------------------------------------------------------------------------
// K4: out[dst] += w * g_h2[src]   (scalar RED, 4-edge ILP)
// ---------------------------------------------------------------------------
__global__ void k_spmm2(const int*   __restrict__ src,
                        const int*   __restrict__ dst,
                        const float* __restrict__ w,
                        float* __restrict__ out, int E, int quarter) {
    int i = blockIdx.x * blockDim.x + threadIdx.x;
    if (i >= quarter) return;

    int  e[4];  bool hv[4];
#pragma unroll
    for (int j = 0; j < 4; ++j) {
        e[j]  = i + j * quarter;
        hv[j] = (e[j] < E);
        if (!hv[j]) e[j] = 0;
    }
    int s[4], d[4]; float ww[4];
#pragma unroll
    for (int j = 0; j < 4; ++j) {
        s[j]  = __ldg(src + e[j]);
        d[j]  = __ldg(dst + e[j]);
        ww[j] = __ldg(w   + e[j]);
    }
    float h[4];
#pragma unroll
    for (int j = 0; j < 4; ++j) h[j] = __ldg(g_h2 + s[j]);
#pragma unroll
    for (int j = 0; j < 4; ++j)
        if (hv[j]) atomicAdd(out + d[j], ww[j] * h[j]);
}

// ---------------------------------------------------------------------------
extern "C" void kernel_launch(void* const* d_in, const int* in_sizes, int n_in,
                              void* d_out, int out_size) {
    const float* x   = (const float*)d_in[0];
    const int*   src = (const int*)  d_in[1];
    const int*   dst = (const int*)  d_in[2];
    const float* w   = (const float*)d_in[3];
    const float* W1  = (const float*)d_in[4];
    const float* b1  = (const float*)d_in[5];
    const float* W2  = (const float*)d_in[6];
    const float* b2  = (const float*)d_in[7];
    float* out = (float*)d_out;

    int N = in_sizes[0] / IN_DIM;
    int E = in_sizes[1];

    const int T = 256;

    // slots 1-3: zero g_h (3-way split; gemm lands in ncu slot 4)
    int n4 = N * HID / 4;
    int c  = (n4 + 2) / 3;
    k_zero<<<(c + T - 1) / T, T>>>(0, c);
    k_zero<<<(c + T - 1) / T, T>>>(c, 2 * c);
    k_zero<<<(c + T - 1) / T, T>>>(2 * c, n4);

    // slot 4 (ncu-sampled): persistent 4-stage pipelined gemm
    cudaFuncSetAttribute(k_gemm1,
        cudaFuncAttributeMaxDynamicSharedMemorySize, GSM_B);
    const int GBLOCKS = 296;                      // 2 blocks/SM, 2 exact waves
    k_gemm1<<<GBLOCKS, 256, GSM_B>>>(x, W1, N, GBLOCKS * GW_B);

    // slot 5: spmm1, 4 threads/edge, 4-edge ILP
    int q1 = (E + 3) >> 2;
    long long t1 = (long long)q1 * 4;
    k_spmm1<<<(unsigned)((t1 + 511) / 512), 512>>>(src, dst, w, E, q1);

    // slot 6: h2 = relu(h + b1) @ W2 ; out = b2
    k_layer2a<<<(N + T - 1) / T, T>>>(b1, W2, b2, out, N);

    // slot 7: out += scatter(w * h2[src]) by dst
    k_spmm2<<<(q1 + 511) / 512, 512>>>(src, dst, w, out, E, q1);
}

// round 8
// speedup vs baseline: 1.0127x; 1.0127x over previous
#include <cuda_runtime.h>
#include <cuda_fp16.h>
#include <cstdint>

#define NMAX    100000
#define IN_DIM  512
#define HID     16

typedef unsigned long long ull;

// Scratch (allocation-free per harness rules): __device__ globals.
__device__ __half g_xw16[(size_t)NMAX * HID];  // x @ W1 (fp16)    [N,16]
__device__ float  g_h [(size_t)NMAX * HID];    // spmm accumulator [N,16]
__device__ float  g_h2[(size_t)NMAX];          // relu(h+b1) @ W2  [N]

// ---------------------------------------------------------------------------
// K0: zero the spmm-1 accumulator (3-way split so gemm1 is ncu's slot 4)
// ---------------------------------------------------------------------------
__global__ void k_zero(int off, int lim) {
    int i = off + blockIdx.x * blockDim.x + threadIdx.x;
    if (i < lim) ((float4*)g_h)[i] = make_float4(0.f, 0.f, 0.f, 0.f);
}

// ---------------------------------------------------------------------------
// K1: g_xw16 = fp16(x @ W1)
//   148 blocks x 12 warps, 32-row chunks, 2 rows/lane x 8 cols/lane.
//   k-pair f32x2 accumulation (no broadcast MOVs), W in paired smem layout.
//   Warp-private 4-stage cp.async pipeline, continuous across chunks.
// ---------------------------------------------------------------------------
#define KT2     16
#define RPW2    32                         // rows per chunk
#define PADW2   20                         // floats per row in smem
#define TILEF2  (RPW2 * PADW2)             // 640 floats per tile buffer
#define STG2    4
#define TPC     (IN_DIM / KT2)             // 32 tiles per chunk
#define GW_B    12                         // warps per block
#define SWP_F   (256 * HID * 2)            // 8192 floats: W pairs
#define GSM_B   ((SWP_F + GW_B * STG2 * TILEF2) * 4)   // 155648 B

#define FF(A, X, W) \
    asm("fma.rn.f32x2 %0, %1, %2, %0;" : "+l"(A) : "l"(X), "l"(W))

#define GLOAD(J)                                                              \
    {                                                                         \
        int j_   = (J);                                                       \
        int kt_  = j_ & (TPC - 1);                                            \
        int ch_  = wg + (j_ >> 5) * nw;                                       \
        float* dst0 = sB + (j_ & (STG2 - 1)) * TILEF2;                        \
        _Pragma("unroll")                                                     \
        for (int i_ = 0; i_ < 4; ++i_) {                                      \
            int flat = i_ * 32 + lane;                                        \
            int r_ = flat >> 2, q_ = flat & 3;                                \
            unsigned d_ = (unsigned)__cvta_generic_to_shared(                 \
                dst0 + r_ * PADW2 + q_ * 4);                                  \
            long row_ = (long)ch_ * RPW2 + r_;                                \
            int ok_ = (row_ < n);                                             \
            const float* s_ = x + (ok_ ? (row_ * IN_DIM                       \
                                          + kt_ * KT2 + q_ * 4) : 0);         \
            int sz_ = ok_ ? 16 : 0;                                           \
            asm volatile("cp.async.cg.shared.global [%0], [%1], 16, %2;"      \
                         :: "r"(d_), "l"(s_), "r"(sz_));                      \
        }                                                                     \
        asm volatile("cp.async.commit_group;");                              \
    }

__device__ __forceinline__ unsigned pk16(float a, float b) {
    __half2 h = __floats2half2_rn(a, b);
    return *reinterpret_cast<unsigned*>(&h);
}

__global__ void __launch_bounds__(384) k_gemm1(
        const float* __restrict__ x,
        const float* __restrict__ W1, int n, int nw) {
    extern __shared__ float sm[];
    float* sWp = sm;                        // [256 k2][16 c] float2

    int t    = threadIdx.x;
    int w    = t >> 5;
    int lane = t & 31;
    float* sB = sm + SWP_F + w * (STG2 * TILEF2);
    int wg    = blockIdx.x * GW_B + w;
    int rlane = lane & 15;
    int half  = lane >> 4;

    int nchunks = (n + RPW2 - 1) / RPW2;
    int myn     = (wg < nchunks) ? ((nchunks - 1 - wg) / nw + 1) : 0;
    int ntiles  = myn * TPC;

    // prologue: 3 tiles in flight (commits 1..3)
    if (ntiles > 0) GLOAD(0);
    if (ntiles > 1) GLOAD(1);
    if (ntiles > 2) GLOAD(2);

    // build paired W layout from gmem (L2-resident, independent loads)
    for (int idx = t; idx < 256 * HID; idx += 384) {
        int k2 = idx >> 4, c = idx & 15;
        float a = __ldg(W1 + (2 * k2) * HID + c);
        float b = __ldg(W1 + (2 * k2 + 1) * HID + c);
        *(float2*)(sWp + (size_t)idx * 2) = make_float2(a, b);
    }
    __syncthreads();                        // sWp visible to all warps

    ull acc0[8], acc1[8];
#pragma unroll
    for (int q = 0; q < 8; ++q) { acc0[q] = 0ull; acc1[q] = 0ull; }

#pragma unroll 1
    for (int j = 0; j < ntiles; ++j) {
        if (j + 3 < ntiles) {
            GLOAD(j + 3);
            asm volatile("cp.async.wait_group 3;");
        } else {
            int r = ntiles - 1 - j;
            if      (r == 2) asm volatile("cp.async.wait_group 2;");
            else if (r == 1) asm volatile("cp.async.wait_group 1;");
            else             asm volatile("cp.async.wait_group 0;");
        }
        __syncwarp();

        int kt = j & (TPC - 1);
        const float* bufp = sB + (j & (STG2 - 1)) * TILEF2;
        const ulonglong2* x0 = (const ulonglong2*)(bufp + rlane * PADW2);
        const ulonglong2* x1 = (const ulonglong2*)(bufp + (rlane + 16) * PADW2);

#pragma unroll
        for (int k4 = 0; k4 < 4; ++k4) {
            ulonglong2 xa = x0[k4];
            ulonglong2 xb = x1[k4];
#pragma unroll
            for (int kp = 0; kp < 2; ++kp) {
                ull xpa = kp ? xa.y : xa.x;
                ull xpb = kp ? xb.y : xb.x;
                int k2 = kt * 8 + k4 * 2 + kp;
                const ulonglong2* wp = (const ulonglong2*)
                    (sWp + (size_t)k2 * 32 + half * 16);
                ulonglong2 w0 = wp[0], w1 = wp[1], w2 = wp[2], w3 = wp[3];
                FF(acc0[0], xpa, w0.x); FF(acc0[1], xpa, w0.y);
                FF(acc0[2], xpa, w1.x); FF(acc0[3], xpa, w1.y);
                FF(acc0[4], xpa, w2.x); FF(acc0[5], xpa, w2.y);
                FF(acc0[6], xpa, w3.x); FF(acc0[7], xpa, w3.y);
                FF(acc1[0], xpb, w0.x); FF(acc1[1], xpb, w0.y);
                FF(acc1[2], xpb, w1.x); FF(acc1[3], xpb, w1.y);
                FF(acc1[4], xpb, w2.x); FF(acc1[5], xpb, w2.y);
                FF(acc1[6], xpb, w3.x); FF(acc1[7], xpb, w3.y);
            }
        }

        if (kt == TPC - 1) {                 // chunk done: collapse + fp16 out
            int chunk = wg + (j >> 5) * nw;
            int row0  = chunk * RPW2 + rlane;
            float f0[8], f1[8];
#pragma unroll
            for (int i = 0; i < 8; ++i) {
                float lo, hi;
                asm("mov.b64 {%0,%1}, %2;" : "=f"(lo), "=f"(hi) : "l"(acc0[i]));
                f0[i] = lo + hi;
                asm("mov.b64 {%0,%1}, %2;" : "=f"(lo), "=f"(hi) : "l"(acc1[i]));
                f1[i] = lo + hi;
                acc0[i] = 0ull; acc1[i] = 0ull;
            }
            uint4 u0 = make_uint4(pk16(f0[0], f0[1]), pk16(f0[2], f0[3]),
                                  pk16(f0[4], f0[5]), pk16(f0[6], f0[7]));
            uint4 u1 = make_uint4(pk16(f1[0], f1[1]), pk16(f1[2], f1[3]),
                                  pk16(f1[4], f1[5]), pk16(f1[6], f1[7]));
            if (row0 < n)
                ((uint4*)g_xw16)[(size_t)row0 * 2 + half] = u0;
            if (row0 + 16 < n)
                ((uint4*)g_xw16)[(size_t)(row0 + 16) * 2 + half] = u1;
        }
    }
}

// ---------------------------------------------------------------------------
// K2: g_h[dst] += w * fp32(g_xw16[src])  (2 threads/edge, 4-edge ILP)
// ---------------------------------------------------------------------------
__global__ void k_spmm1(const int*   __restrict__ src,
                        const int*   __restrict__ dst,
                        const float* __restrict__ w, int E, int quarter) {
    int t = blockIdx.x * blockDim.x + threadIdx.x;
    int i = t >> 1;
    if (i >= quarter) return;
    int part = t & 1;

    int  e[4];  bool hv[4];
#pragma unroll
    for (int j = 0; j < 4; ++j) {
        e[j]  = i + j * quarter;
        hv[j] = (e[j] < E);
        if (!hv[j]) e[j] = 0;
    }

    int s[4], d[4]; float ww[4];
#pragma unroll
    for (int j = 0; j < 4; ++j) {
        s[j]  = __ldg(src + e[j]);
        d[j]  = __ldg(dst + e[j]);
        ww[j] = __ldg(w   + e[j]);
    }

    uint4 v[4];
#pragma unroll
    for (int j = 0; j < 4; ++j)
        v[j] = __ldg(((const uint4*)g_xw16) + (size_t)s[j] * 2 + part);

#pragma unroll
    for (int j = 0; j < 4; ++j) {
        if (!hv[j]) continue;
        float2 f0 = __half22float2(*reinterpret_cast<__half2*>(&v[j].x));
        float2 f1 = __half22float2(*reinterpret_cast<__half2*>(&v[j].y));
        float2 f2 = __half22float2(*reinterpret_cast<__half2*>(&v[j].z));
        float2 f3 = __half22float2(*reinterpret_cast<__half2*>(&v[j].w));
        float we = ww[j];
        float* a = g_h + (((size_t)d[j]) << 4) + (part << 3);
        asm volatile("red.global.add.v4.f32 [%0], {%1, %2, %3, %4};"
                     :: "l"(a), "f"(f0.x * we), "f"(f0.y * we),
                        "f"(f1.x * we), "f"(f1.y * we) : "memory");
        asm volatile("red.global.add.v4.f32 [%0], {%1, %2, %3, %4};"
                     :: "l"(a + 4), "f"(f2.x * we), "f"(f2.y * we),
                        "f"(f3.x * we), "f"(f3.y * we) : "memory");
    }
}

// ---------------------------------------------------------------------------
// K3: g_h2 = relu(g_h + b1) @ W2 ; out init to b2
// ---------------------------------------------------------------------------
__global__ void k_layer2a(const float* __restrict__ b1,
                          const float* __restrict__ W2,
                          const float* __restrict__ b2,
                          float* __restrict__ out, int n) {
    int i = blockIdx.x * blockDim.x + threadIdx.x;
    if (i >= n) return;
    float acc = 0.f;
#pragma unroll
    for (int p = 0; p < 4; ++p) {
        float4 hv = ((const float4*)g_h)[(size_t)i * 4 + p];
        float4 bv = __ldg(((const float4*)b1) + p);
        float4 wv = __ldg(((const float4*)W2) + p);
        acc += fmaxf(hv.x + bv.x, 0.f) * wv.x
             + fmaxf(hv.y + bv.y, 0.f) * wv.y
             + fmaxf(hv.z + bv.z, 0.f) * wv.z
             + fmaxf(hv.w + bv.w, 0.f) * wv.w;
    }
    g_h2[i] = acc;
    out[i]  = __ldg(b2);
}

// ---------------------------------------------------------------------------
// K4: out[dst] += w * g_h2[src]   (scalar RED, 4-edge ILP)
// ---------------------------------------------------------------------------
__global__ void k_spmm2(const int*   __restrict__ src,
                        const int*   __restrict__ dst,
                        const float* __restrict__ w,
                        float* __restrict__ out, int E, int quarter) {
    int i = blockIdx.x * blockDim.x + threadIdx.x;
    if (i >= quarter) return;

    int  e[4];  bool hv[4];
#pragma unroll
    for (int j = 0; j < 4; ++j) {
        e[j]  = i + j * quarter;
        hv[j] = (e[j] < E);
        if (!hv[j]) e[j] = 0;
    }
    int s[4], d[4]; float ww[4];
#pragma unroll
    for (int j = 0; j < 4; ++j) {
        s[j]  = __ldg(src + e[j]);
        d[j]  = __ldg(dst + e[j]);
        ww[j] = __ldg(w   + e[j]);
    }
    float h[4];
#pragma unroll
    for (int j = 0; j < 4; ++j) h[j] = __ldg(g_h2 + s[j]);
#pragma unroll
    for (int j = 0; j < 4; ++j)
        if (hv[j]) atomicAdd(out + d[j], ww[j] * h[j]);
}

// ---------------------------------------------------------------------------
extern "C" void kernel_launch(void* const* d_in, const int* in_sizes, int n_in,
                              void* d_out, int out_size) {
    const float* x   = (const float*)d_in[0];
    const int*   src = (const int*)  d_in[1];
    const int*   dst = (const int*)  d_in[2];
    const float* w   = (const float*)d_in[3];
    const float* W1  = (const float*)d_in[4];
    const float* b1  = (const float*)d_in[5];
    const float* W2  = (const float*)d_in[6];
    const float* b2  = (const float*)d_in[7];
    float* out = (float*)d_out;

    int N = in_sizes[0] / IN_DIM;
    int E = in_sizes[1];

    const int T = 256;

    // slots 1-3: zero g_h (gemm lands in ncu slot 4)
    int n4 = N * HID / 4;
    int c  = (n4 + 2) / 3;
    k_zero<<<(c + T - 1) / T, T>>>(0, c);
    k_zero<<<(c + T - 1) / T, T>>>(c, 2 * c);
    k_zero<<<(c + T - 1) / T, T>>>(2 * c, n4);

    // slot 4 (ncu-sampled): k-pair f32x2 gemm, fp16 output
    cudaFuncSetAttribute(k_gemm1,
        cudaFuncAttributeMaxDynamicSharedMemorySize, GSM_B);
    const int GB = 148;
    k_gemm1<<<GB, 384, GSM_B>>>(x, W1, N, GB * GW_B);

    // slot 5: spmm1, 2 threads/edge (fp16 gather), 4-edge ILP
    int q1 = (E + 3) >> 2;
    long long t1 = (long long)q1 * 2;
    k_spmm1<<<(unsigned)((t1 + 511) / 512), 512>>>(src, dst, w, E, q1);

    // slot 6: h2 = relu(h + b1) @ W2 ; out = b2
    k_layer2a<<<(N + T - 1) / T, T>>>(b1, W2, b2, out, N);

    // slot 7: out += scatter(w * h2[src]) by dst
    k_spmm2<<<(q1 + 511) / 512, 512>>>(src, dst, w, out, E, q1);
}

// round 10
// speedup vs baseline: 1.0243x; 1.0115x over previous
#include <cuda_runtime.h>
#include <cuda_fp16.h>
#include <cstdint>

#define NMAX    100000
#define IN_DIM  512
#define HID     16

typedef unsigned long long ull;

// Scratch (allocation-free per harness rules): __device__ globals.
__device__ __half g_xw16[(size_t)NMAX * HID];  // x @ W1 (fp16)    [N,16]
__device__ float  g_h [(size_t)NMAX * HID];    // spmm accumulator [N,16]
__device__ float  g_h2[(size_t)NMAX];          // relu(h+b1) @ W2  [N]

// ---------------------------------------------------------------------------
// K0: zero the spmm-1 accumulator (3-way split so gemm1 is ncu's slot 4)
// ---------------------------------------------------------------------------
__global__ void k_zero(int off, int lim) {
    int i = off + blockIdx.x * blockDim.x + threadIdx.x;
    if (i < lim) ((float4*)g_h)[i] = make_float4(0.f, 0.f, 0.f, 0.f);
}

// ---------------------------------------------------------------------------
// K1: g_xw16 = fp16(x @ W1)
//   296 blocks x 12 warps (2 blocks/SM -> 24 warps/SM), one 32-row chunk per
//   warp, 2 rows/lane x 8 cols/lane, k-pair f32x2 accumulation, warp-private
//   2-stage cp.async pipeline with lookahead 1 (lookahead < stages!).
// ---------------------------------------------------------------------------
#define KT2     16
#define RPW2    32                         // rows per chunk
#define PADW2   20                         // floats per row in smem
#define TILEF2  (RPW2 * PADW2)             // 640 floats per tile buffer
#define STG2    2
#define TPC     (IN_DIM / KT2)             // 32 tiles per chunk
#define GW_B    12                         // warps per block
#define SWP_F   (256 * HID * 2)            // 8192 floats: W pairs
#define GSM_B   ((SWP_F + GW_B * STG2 * TILEF2) * 4)   // 94208 B

#define FF(A, X, W) \
    asm("fma.rn.f32x2 %0, %1, %2, %0;" : "+l"(A) : "l"(X), "l"(W))

#define GLOAD(J)                                                              \
    {                                                                         \
        int j_   = (J);                                                       \
        int kt_  = j_ & (TPC - 1);                                            \
        int ch_  = wg + (j_ >> 5) * nw;                                       \
        float* dst0 = sB + (j_ & (STG2 - 1)) * TILEF2;                        \
        _Pragma("unroll")                                                     \
        for (int i_ = 0; i_ < 4; ++i_) {                                      \
            int flat = i_ * 32 + lane;                                        \
            int r_ = flat >> 2, q_ = flat & 3;                                \
            unsigned d_ = (unsigned)__cvta_generic_to_shared(                 \
                dst0 + r_ * PADW2 + q_ * 4);                                  \
            long row_ = (long)ch_ * RPW2 + r_;                                \
            int ok_ = (row_ < n);                                             \
            const float* s_ = x + (ok_ ? (row_ * IN_DIM                       \
                                          + kt_ * KT2 + q_ * 4) : 0);         \
            int sz_ = ok_ ? 16 : 0;                                           \
            asm volatile("cp.async.cg.shared.global [%0], [%1], 16, %2;"      \
                         :: "r"(d_), "l"(s_), "r"(sz_));                      \
        }                                                                     \
        asm volatile("cp.async.commit_group;");                              \
    }

__device__ __forceinline__ unsigned pk16(float a, float b) {
    __half2 h = __floats2half2_rn(a, b);
    return *reinterpret_cast<unsigned*>(&h);
}

__global__ void __launch_bounds__(384) k_gemm1(
        const float* __restrict__ x,
        const float* __restrict__ W1, int n, int nw) {
    extern __shared__ float sm[];
    float* sWp = sm;                        // [256 k2][16 c] float2

    int t    = threadIdx.x;
    int w    = t >> 5;
    int lane = t & 31;
    float* sB = sm + SWP_F + w * (STG2 * TILEF2);
    int wg    = blockIdx.x * GW_B + w;
    int rlane = lane & 15;
    int half  = lane >> 4;

    int nchunks = (n + RPW2 - 1) / RPW2;
    int myn     = (wg < nchunks) ? ((nchunks - 1 - wg) / nw + 1) : 0;
    int ntiles  = myn * TPC;

    // prologue: tile 0 in flight (buffer 0)
    if (ntiles > 0) GLOAD(0);

    // build paired W layout from gmem (L2-resident, independent loads)
    for (int idx = t; idx < 256 * HID; idx += 384) {
        int k2 = idx >> 4, c = idx & 15;
        float a = __ldg(W1 + (2 * k2) * HID + c);
        float b = __ldg(W1 + (2 * k2 + 1) * HID + c);
        *(float2*)(sWp + (size_t)idx * 2) = make_float2(a, b);
    }
    __syncthreads();                        // sWp visible to all warps

    ull acc0[8], acc1[8];
#pragma unroll
    for (int q = 0; q < 8; ++q) { acc0[q] = 0ull; acc1[q] = 0ull; }

#pragma unroll 1
    for (int j = 0; j < ntiles; ++j) {
        if (j + 1 < ntiles) {
            GLOAD(j + 1);                    // buffer (j+1)&1 != j&1
            asm volatile("cp.async.wait_group 1;");   // tile j complete
        } else {
            asm volatile("cp.async.wait_group 0;");
        }
        __syncwarp();

        int kt = j & (TPC - 1);
        const float* bufp = sB + (j & (STG2 - 1)) * TILEF2;
        const ulonglong2* x0 = (const ulonglong2*)(bufp + rlane * PADW2);
        const ulonglong2* x1 = (const ulonglong2*)(bufp + (rlane + 16) * PADW2);

#pragma unroll
        for (int k4 = 0; k4 < 4; ++k4) {
            ulonglong2 xa = x0[k4];
            ulonglong2 xb = x1[k4];
#pragma unroll
            for (int kp = 0; kp < 2; ++kp) {
                ull xpa = kp ? xa.y : xa.x;
                ull xpb = kp ? xb.y : xb.x;
                int k2 = kt * 8 + k4 * 2 + kp;
                const ulonglong2* wp = (const ulonglong2*)
                    (sWp + (size_t)k2 * 32 + half * 16);
                ulonglong2 w0 = wp[0], w1 = wp[1], w2 = wp[2], w3 = wp[3];
                FF(acc0[0], xpa, w0.x); FF(acc0[1], xpa, w0.y);
                FF(acc0[2], xpa, w1.x); FF(acc0[3], xpa, w1.y);
                FF(acc0[4], xpa, w2.x); FF(acc0[5], xpa, w2.y);
                FF(acc0[6], xpa, w3.x); FF(acc0[7], xpa, w3.y);
                FF(acc1[0], xpb, w0.x); FF(acc1[1], xpb, w0.y);
                FF(acc1[2], xpb, w1.x); FF(acc1[3], xpb, w1.y);
                FF(acc1[4], xpb, w2.x); FF(acc1[5], xpb, w2.y);
                FF(acc1[6], xpb, w3.x); FF(acc1[7], xpb, w3.y);
            }
        }

        if (kt == TPC - 1) {                 // chunk done: collapse + fp16 out
            int chunk = wg + (j >> 5) * nw;
            int row0  = chunk * RPW2 + rlane;
            float f0[8], f1[8];
#pragma unroll
            for (int i = 0; i < 8; ++i) {
                float lo, hi;
                asm("mov.b64 {%0,%1}, %2;" : "=f"(lo), "=f"(hi) : "l"(acc0[i]));
                f0[i] = lo + hi;
                asm("mov.b64 {%0,%1}, %2;" : "=f"(lo), "=f"(hi) : "l"(acc1[i]));
                f1[i] = lo + hi;
                acc0[i] = 0ull; acc1[i] = 0ull;
            }
            uint4 u0 = make_uint4(pk16(f0[0], f0[1]), pk16(f0[2], f0[3]),
                                  pk16(f0[4], f0[5]), pk16(f0[6], f0[7]));
            uint4 u1 = make_uint4(pk16(f1[0], f1[1]), pk16(f1[2], f1[3]),
                                  pk16(f1[4], f1[5]), pk16(f1[6], f1[7]));
            if (row0 < n)
                ((uint4*)g_xw16)[(size_t)row0 * 2 + half] = u0;
            if (row0 + 16 < n)
                ((uint4*)g_xw16)[(size_t)(row0 + 16) * 2 + half] = u1;
        }
    }
}

// ---------------------------------------------------------------------------
// K2: g_h[dst] += w * fp32(g_xw16[src])  (2 threads/edge, 4-edge ILP)
// ---------------------------------------------------------------------------
__global__ void k_spmm1(const int*   __restrict__ src,
                        const int*   __restrict__ dst,
                        const float* __restrict__ w, int E, int quarter) {
    int t = blockIdx.x * blockDim.x + threadIdx.x;
    int i = t >> 1;
    if (i >= quarter) return;
    int part = t & 1;

    int  e[4];  bool hv[4];
#pragma unroll
    for (int j = 0; j < 4; ++j) {
        e[j]  = i + j * quarter;
        hv[j] = (e[j] < E);
        if (!hv[j]) e[j] = 0;
    }

    int s[4], d[4]; float ww[4];
#pragma unroll
    for (int j = 0; j < 4; ++j) {
        s[j]  = __ldg(src + e[j]);
        d[j]  = __ldg(dst + e[j]);
        ww[j] = __ldg(w   + e[j]);
    }

    uint4 v[4];
#pragma unroll
    for (int j = 0; j < 4; ++j)
        v[j] = __ldg(((const uint4*)g_xw16) + (size_t)s[j] * 2 + part);

#pragma unroll
    for (int j = 0; j < 4; ++j) {
        if (!hv[j]) continue;
        float2 f0 = __half22float2(*reinterpret_cast<__half2*>(&v[j].x));
        float2 f1 = __half22float2(*reinterpret_cast<__half2*>(&v[j].y));
        float2 f2 = __half22float2(*reinterpret_cast<__half2*>(&v[j].z));
        float2 f3 = __half22float2(*reinterpret_cast<__half2*>(&v[j].w));
        float we = ww[j];
        float* a = g_h + (((size_t)d[j]) << 4) + (part << 3);
        asm volatile("red.global.add.v4.f32 [%0], {%1, %2, %3, %4};"
                     :: "l"(a), "f"(f0.x * we), "f"(f0.y * we),
                        "f"(f1.x * we), "f"(f1.y * we) : "memory");
        asm volatile("red.global.add.v4.f32 [%0], {%1, %2, %3, %4};"
                     :: "l"(a + 4), "f"(f2.x * we), "f"(f2.y * we),
                        "f"(f3.x * we), "f"(f3.y * we) : "memory");
    }
}

// ---------------------------------------------------------------------------
// K3: g_h2 = relu(g_h + b1) @ W2 ; out init to b2
// ---------------------------------------------------------------------------
__global__ void k_layer2a(const float* __restrict__ b1,
                          const float* __restrict__ W2,
                          const float* __restrict__ b2,
                          float* __restrict__ out, int n) {
    int i = blockIdx.x * blockDim.x + threadIdx.x;
    if (i >= n) return;
    float acc = 0.f;
#pragma unroll
    for (int p = 0; p < 4; ++p) {
        float4 hv = ((const float4*)g_h)[(size_t)i * 4 + p];
        float4 bv = __ldg(((const float4*)b1) + p);
        float4 wv = __ldg(((const float4*)W2) + p);
        acc += fmaxf(hv.x + bv.x, 0.f) * wv.x
             + fmaxf(hv.y + bv.y, 0.f) * wv.y
             + fmaxf(hv.z + bv.z, 0.f) * wv.z
             + fmaxf(hv.w + bv.w, 0.f) * wv.w;
    }
    g_h2[i] = acc;
    out[i]  = __ldg(b2);
}

// ---------------------------------------------------------------------------
// K4: out[dst] += w * g_h2[src]   (scalar RED, 4-edge ILP)
// ---------------------------------------------------------------------------
__global__ void k_spmm2(const int*   __restrict__ src,
                        const int*   __restrict__ dst,
                        const float* __restrict__ w,
                        float* __restrict__ out, int E, int quarter) {
    int i = blockIdx.x * blockDim.x + threadIdx.x;
    if (i >= quarter) return;

    int  e[4];  bool hv[4];
#pragma unroll
    for (int j = 0; j < 4; ++j) {
        e[j]  = i + j * quarter;
        hv[j] = (e[j] < E);
        if (!hv[j]) e[j] = 0;
    }
    int s[4], d[4]; float ww[4];
#pragma unroll
    for (int j = 0; j < 4; ++j) {
        s[j]  = __ldg(src + e[j]);
        d[j]  = __ldg(dst + e[j]);
        ww[j] = __ldg(w   + e[j]);
    }
    float h[4];
#pragma unroll
    for (int j = 0; j < 4; ++j) h[j] = __ldg(g_h2 + s[j]);
#pragma unroll
    for (int j = 0; j < 4; ++j)
        if (hv[j]) atomicAdd(out + d[j], ww[j] * h[j]);
}

// ---------------------------------------------------------------------------
extern "C" void kernel_launch(void* const* d_in, const int* in_sizes, int n_in,
                              void* d_out, int out_size) {
    const float* x   = (const float*)d_in[0];
    const int*   src = (const int*)  d_in[1];
    const int*   dst = (const int*)  d_in[2];
    const float* w   = (const float*)d_in[3];
    const float* W1  = (const float*)d_in[4];
    const float* b1  = (const float*)d_in[5];
    const float* W2  = (const float*)d_in[6];
    const float* b2  = (const float*)d_in[7];
    float* out = (float*)d_out;

    int N = in_sizes[0] / IN_DIM;
    int E = in_sizes[1];

    const int T = 256;

    // slots 1-3: zero g_h (gemm lands in ncu slot 4)
    int n4 = N * HID / 4;
    int c  = (n4 + 2) / 3;
    k_zero<<<(c + T - 1) / T, T>>>(0, c);
    k_zero<<<(c + T - 1) / T, T>>>(c, 2 * c);
    k_zero<<<(c + T - 1) / T, T>>>(2 * c, n4);

    // slot 4 (ncu-sampled): k-pair f32x2 gemm, 2 blocks/SM, 24 warps/SM
    cudaFuncSetAttribute(k_gemm1,
        cudaFuncAttributeMaxDynamicSharedMemorySize, GSM_B);
    const int GB = 296;
    k_gemm1<<<GB, 384, GSM_B>>>(x, W1, N, GB * GW_B);

    // slot 5: spmm1, 2 threads/edge (fp16 gather), 4-edge ILP
    int q1 = (E + 3) >> 2;
    long long t1 = (long long)q1 * 2;
    k_spmm1<<<(unsigned)((t1 + 511) / 512), 512>>>(src, dst, w, E, q1);

    // slot 6: h2 = relu(h + b1) @ W2 ; out = b2
    k_layer2a<<<(N + T - 1) / T, T>>>(b1, W2, b2, out, N);

    // slot 7: out += scatter(w * h2[src]) by dst
    k_spmm2<<<(q1 + 511) / 512, 512>>>(src, dst, w, out, E, q1);
}

// round 11
// speedup vs baseline: 1.1017x; 1.0755x over previous
#include <cuda_runtime.h>
#include <cuda_fp16.h>
#include <cstdint>

#define NMAX    100000
#define IN_DIM  512
#define HID     16

typedef unsigned long long ull;

// Scratch (allocation-free per harness rules): __device__ globals.
__device__ __half g_xw16[(size_t)NMAX * HID];  // x @ W1 (fp16)    [N,16]
__device__ float  g_h [(size_t)NMAX * HID];    // spmm accumulator [N,16]
__device__ float  g_h2[(size_t)NMAX];          // relu(h+b1) @ W2  [N]

// ---------------------------------------------------------------------------
// K0: zero the spmm-1 accumulator (3-way split so gemm1 is ncu's slot 4)
// ---------------------------------------------------------------------------
__global__ void k_zero(int off, int lim) {
    int i = off + blockIdx.x * blockDim.x + threadIdx.x;
    if (i < lim) ((float4*)g_h)[i] = make_float4(0.f, 0.f, 0.f, 0.f);
}

// ---------------------------------------------------------------------------
// K1: g_xw16 = fp16(x @ W1) via tf32 mma.sync (m16n8k8).
//   296 blocks x 12 warps (2 blocks/SM), one 32-row chunk per warp.
//   W1 pre-swizzled to fragment-major smem (tf32, conflict-free LDS.64);
//   x tiles (32r x 16k) via warp-private 2-stage cp.async, PAD=20 so
//   fragment A loads are bank-conflict-free (bank = 4*grp + tig).
// ---------------------------------------------------------------------------
#define KT3     16
#define RPW3    32                          // rows per chunk
#define PADW3   20                          // floats per smem row
#define TILEF3  (RPW3 * PADW3)              // 640 floats / 2560 B per buffer
#define TPC3    (IN_DIM / KT3)              // 32 tiles per chunk
#define GW3     12                          // warps per block
#define SB2_F2  (64 * 2 * 32)               // 4096 float2 = 32 KB (B frags)
#define GSM_B   (SB2_F2 * 8 + GW3 * 2 * TILEF3 * 4)   // 94208 B

#define MMA_TF32(C, A, B0, B1)                                                \
    asm("mma.sync.aligned.m16n8k8.row.col.f32.tf32.tf32.f32 "                 \
        "{%0,%1,%2,%3}, {%4,%5,%6,%7}, {%8,%9}, {%0,%1,%2,%3};"               \
        : "+f"((C)[0]), "+f"((C)[1]), "+f"((C)[2]), "+f"((C)[3])              \
        : "r"((A)[0]), "r"((A)[1]), "r"((A)[2]), "r"((A)[3]),                 \
          "r"(B0), "r"(B1))

#define GLOAD3(J)                                                             \
    {                                                                         \
        int j_ = (J);                                                         \
        float* dst0 = sB + (j_ & 1) * TILEF3;                                 \
        _Pragma("unroll")                                                     \
        for (int i_ = 0; i_ < 4; ++i_) {                                      \
            int flat = i_ * 32 + lane;                                        \
            int r_ = flat >> 2, q_ = flat & 3;                                \
            unsigned d_ = (unsigned)__cvta_generic_to_shared(                 \
                dst0 + r_ * PADW3 + q_ * 4);                                  \
            long row_ = (long)wg * RPW3 + r_;                                 \
            int ok_ = (row_ < n);                                             \
            const float* s_ = x + (ok_ ? (row_ * IN_DIM                       \
                                          + j_ * KT3 + q_ * 4) : 0);          \
            int sz_ = ok_ ? 16 : 0;                                           \
            asm volatile("cp.async.cg.shared.global [%0], [%1], 16, %2;"      \
                         :: "r"(d_), "l"(s_), "r"(sz_));                      \
        }                                                                     \
        asm volatile("cp.async.commit_group;");                              \
    }

__device__ __forceinline__ unsigned tf32b(float v) {
    unsigned u;
    asm("cvt.rna.tf32.f32 %0, %1;" : "=r"(u) : "f"(v));
    return u;
}

__global__ void __launch_bounds__(384) k_gemm1(
        const float* __restrict__ x,
        const float* __restrict__ W1, int n, int nw) {
    extern __shared__ float sm[];
    float2* sB2 = (float2*)sm;              // [64 kstep][2 nt][32 lane]
    float*  sX0 = sm + SB2_F2 * 2;

    int t    = threadIdx.x;
    int w    = t >> 5;
    int lane = t & 31;
    int grp  = lane >> 2;
    int tig  = lane & 3;
    float* sB = sX0 + w * (2 * TILEF3);
    int wg    = blockIdx.x * GW3 + w;

    int nchunks = (n + RPW3 - 1) / RPW3;
    bool active = (wg < nchunks);

    if (active) GLOAD3(0);                  // prologue: tile 0 in flight

    // build B fragments: sB2[(kstep*2+nt)*32 + lane] =
    //   ( tf32(W1[kstep*8+tig][nt*8+grp]), tf32(W1[kstep*8+tig+4][nt*8+grp]) )
    for (int idx = t; idx < SB2_F2; idx += 384) {
        int lane2 = idx & 31;
        int nt    = (idx >> 5) & 1;
        int kstep = idx >> 6;
        int g2 = lane2 >> 2, t2 = lane2 & 3;
        int k0 = kstep * 8 + t2;
        int n0 = nt * 8 + g2;
        float b0 = __ldg(W1 + k0 * HID + n0);
        float b1 = __ldg(W1 + (k0 + 4) * HID + n0);
        unsigned u0 = tf32b(b0), u1 = tf32b(b1);
        sB2[idx] = make_float2(__uint_as_float(u0), __uint_as_float(u1));
    }
    __syncthreads();

    if (!active) return;

    float c[2][2][4];
#pragma unroll
    for (int mt = 0; mt < 2; ++mt)
#pragma unroll
        for (int nt = 0; nt < 2; ++nt)
#pragma unroll
            for (int q = 0; q < 4; ++q) c[mt][nt][q] = 0.f;

#pragma unroll 1
    for (int j = 0; j < TPC3; ++j) {
        if (j + 1 < TPC3) {
            GLOAD3(j + 1);
            asm volatile("cp.async.wait_group 1;");
        } else {
            asm volatile("cp.async.wait_group 0;");
        }
        __syncwarp();

        const float* sX = sB + (j & 1) * TILEF3;
#pragma unroll
        for (int kk = 0; kk < 2; ++kk) {
            unsigned a[2][4];
#pragma unroll
            for (int mt = 0; mt < 2; ++mt) {
                int r0 = mt * 16 + grp;
                const float* p0 = sX + r0 * PADW3 + kk * 8 + tig;
                const float* p1 = p0 + 8 * PADW3;
                a[mt][0] = __float_as_uint(p0[0]);
                a[mt][1] = __float_as_uint(p1[0]);
                a[mt][2] = __float_as_uint(p0[4]);
                a[mt][3] = __float_as_uint(p1[4]);
            }
            int kstep = j * 2 + kk;
#pragma unroll
            for (int nt = 0; nt < 2; ++nt) {
                float2 b = sB2[(kstep * 2 + nt) * 32 + lane];
                unsigned b0 = __float_as_uint(b.x);
                unsigned b1 = __float_as_uint(b.y);
                MMA_TF32(c[0][nt], a[0], b0, b1);
                MMA_TF32(c[1][nt], a[1], b0, b1);
            }
        }
    }

    // epilogue: fp16 store.  c[mt][nt]: rows mt*16+grp(+8), cols nt*8+2tig(+1)
    long rowb = (long)wg * RPW3;
#pragma unroll
    for (int mt = 0; mt < 2; ++mt) {
#pragma unroll
        for (int nt = 0; nt < 2; ++nt) {
            long r0 = rowb + mt * 16 + grp;
            int  cb = nt * 8 + 2 * tig;
            __half2 h0 = __floats2half2_rn(c[mt][nt][0], c[mt][nt][1]);
            __half2 h1 = __floats2half2_rn(c[mt][nt][2], c[mt][nt][3]);
            if (r0 < n)
                *(__half2*)(g_xw16 + r0 * HID + cb) = h0;
            if (r0 + 8 < n)
                *(__half2*)(g_xw16 + (r0 + 8) * HID + cb) = h1;
        }
    }
}

// ---------------------------------------------------------------------------
// K2: g_h[dst] += w * fp32(g_xw16[src])  (2 threads/edge, 4-edge ILP)
// ---------------------------------------------------------------------------
__global__ void k_spmm1(const int*   __restrict__ src,
                        const int*   __restrict__ dst,
                        const float* __restrict__ w, int E, int quarter) {
    int t = blockIdx.x * blockDim.x + threadIdx.x;
    int i = t >> 1;
    if (i >= quarter) return;
    int part = t & 1;

    int  e[4];  bool hv[4];
#pragma unroll
    for (int j = 0; j < 4; ++j) {
        e[j]  = i + j * quarter;
        hv[j] = (e[j] < E);
        if (!hv[j]) e[j] = 0;
    }

    int s[4], d[4]; float ww[4];
#pragma unroll
    for (int j = 0; j < 4; ++j) {
        s[j]  = __ldg(src + e[j]);
        d[j]  = __ldg(dst + e[j]);
        ww[j] = __ldg(w   + e[j]);
    }

    uint4 v[4];
#pragma unroll
    for (int j = 0; j < 4; ++j)
        v[j] = __ldg(((const uint4*)g_xw16) + (size_t)s[j] * 2 + part);

#pragma unroll
    for (int j = 0; j < 4; ++j) {
        if (!hv[j]) continue;
        float2 f0 = __half22float2(*reinterpret_cast<__half2*>(&v[j].x));
        float2 f1 = __half22float2(*reinterpret_cast<__half2*>(&v[j].y));
        float2 f2 = __half22float2(*reinterpret_cast<__half2*>(&v[j].z));
        float2 f3 = __half22float2(*reinterpret_cast<__half2*>(&v[j].w));
        float we = ww[j];
        float* a = g_h + (((size_t)d[j]) << 4) + (part << 3);
        asm volatile("red.global.add.v4.f32 [%0], {%1, %2, %3, %4};"
                     :: "l"(a), "f"(f0.x * we), "f"(f0.y * we),
                        "f"(f1.x * we), "f"(f1.y * we) : "memory");
        asm volatile("red.global.add.v4.f32 [%0], {%1, %2, %3, %4};"
                     :: "l"(a + 4), "f"(f2.x * we), "f"(f2.y * we),
                        "f"(f3.x * we), "f"(f3.y * we) : "memory");
    }
}

// ---------------------------------------------------------------------------
// K3: g_h2 = relu(g_h + b1) @ W2 ; out init to b2
// ---------------------------------------------------------------------------
__global__ void k_layer2a(const float* __restrict__ b1,
                          const float* __restrict__ W2,
                          const float* __restrict__ b2,
                          float* __restrict__ out, int n) {
    int i = blockIdx.x * blockDim.x + threadIdx.x;
    if (i >= n) return;
    float acc = 0.f;
#pragma unroll
    for (int p = 0; p < 4; ++p) {
        float4 hv = ((const float4*)g_h)[(size_t)i * 4 + p];
        float4 bv = __ldg(((const float4*)b1) + p);
        float4 wv = __ldg(((const float4*)W2) + p);
        acc += fmaxf(hv.x + bv.x, 0.f) * wv.x
             + fmaxf(hv.y + bv.y, 0.f) * wv.y
             + fmaxf(hv.z + bv.z, 0.f) * wv.z
             + fmaxf(hv.w + bv.w, 0.f) * wv.w;
    }
    g_h2[i] = acc;
    out[i]  = __ldg(b2);
}

// ---------------------------------------------------------------------------
// K4: out[dst] += w * g_h2[src]   (scalar RED, 4-edge ILP)
// ---------------------------------------------------------------------------
__global__ void k_spmm2(const int*   __restrict__ src,
                        const int*   __restrict__ dst,
                        const float* __restrict__ w,
                        float* __restrict__ out, int E, int quarter) {
    int i = blockIdx.x * blockDim.x + threadIdx.x;
    if (i >= quarter) return;

    int  e[4];  bool hv[4];
#pragma unroll
    for (int j = 0; j < 4; ++j) {
        e[j]  = i + j * quarter;
        hv[j] = (e[j] < E);
        if (!hv[j]) e[j] = 0;
    }
    int s[4], d[4]; float ww[4];
#pragma unroll
    for (int j = 0; j < 4; ++j) {
        s[j]  = __ldg(src + e[j]);
        d[j]  = __ldg(dst + e[j]);
        ww[j] = __ldg(w   + e[j]);
    }
    float h[4];
#pragma unroll
    for (int j = 0; j < 4; ++j) h[j] = __ldg(g_h2 + s[j]);
#pragma unroll
    for (int j = 0; j < 4; ++j)
        if (hv[j]) atomicAdd(out + d[j], ww[j] * h[j]);
}

// ---------------------------------------------------------------------------
extern "C" void kernel_launch(void* const* d_in, const int* in_sizes, int n_in,
                              void* d_out, int out_size) {
    const float* x   = (const float*)d_in[0];
    const int*   src = (const int*)  d_in[1];
    const int*   dst = (const int*)  d_in[2];
    const float* w   = (const float*)d_in[3];
    const float* W1  = (const float*)d_in[4];
    const float* b1  = (const float*)d_in[5];
    const float* W2  = (const float*)d_in[6];
    const float* b2  = (const float*)d_in[7];
    float* out = (float*)d_out;

    int N = in_sizes[0] / IN_DIM;
    int E = in_sizes[1];

    const int T = 256;

    // slots 1-3: zero g_h (gemm lands in ncu slot 4)
    int n4 = N * HID / 4;
    int c  = (n4 + 2) / 3;
    k_zero<<<(c + T - 1) / T, T>>>(0, c);
    k_zero<<<(c + T - 1) / T, T>>>(c, 2 * c);
    k_zero<<<(c + T - 1) / T, T>>>(2 * c, n4);

    // slot 4 (ncu-sampled): tf32 tensor-core gemm
    cudaFuncSetAttribute(k_gemm1,
        cudaFuncAttributeMaxDynamicSharedMemorySize, GSM_B);
    const int GB = 296;
    k_gemm1<<<GB, 384, GSM_B>>>(x, W1, N, GB * GW3);

    // slot 5: spmm1, 2 threads/edge (fp16 gather), 4-edge ILP
    int q1 = (E + 3) >> 2;
    long long t1 = (long long)q1 * 2;
    k_spmm1<<<(unsigned)((t1 + 511) / 512), 512>>>(src, dst, w, E, q1);

    // slot 6: h2 = relu(h + b1) @ W2 ; out = b2
    k_layer2a<<<(N + T - 1) / T, T>>>(b1, W2, b2, out, N);

    // slot 7: out += scatter(w * h2[src]) by dst
    k_spmm2<<<(q1 + 511) / 512, 512>>>(src, dst, w, out, E, q1);
}

// round 12
// speedup vs baseline: 1.2415x; 1.1270x over previous
#include <cuda_runtime.h>
#include <cuda_fp16.h>
#include <cstdint>

#define NMAX    100000
#define IN_DIM  512
#define HID     16

typedef unsigned long long ull;

// Scratch (allocation-free per harness rules): __device__ globals.
__device__ __half g_xw16[(size_t)NMAX * HID];  // x @ W1 (fp16)    [N,16]
__device__ float  g_h [(size_t)NMAX * HID];    // spmm accumulator [N,16]
__device__ float  g_h2[(size_t)NMAX];          // relu(h+b1) @ W2  [N]
__device__ float2 g_bfrag[64 * 2 * 32];        // tf32 B fragments [kstep][nt][lane]

// ---------------------------------------------------------------------------
// K0: zero the spmm-1 accumulator
// ---------------------------------------------------------------------------
__global__ void k_zero(int n4) {
    int i = blockIdx.x * blockDim.x + threadIdx.x;
    if (i < n4) ((float4*)g_h)[i] = make_float4(0.f, 0.f, 0.f, 0.f);
}

// ---------------------------------------------------------------------------
// K0b: build tf32 B fragments from W1 (once per call; 32 KB, L2-resident)
//   g_bfrag[(kstep*2+nt)*32 + lane] =
//     ( tf32(W1[kstep*8+tig][nt*8+grp]), tf32(W1[kstep*8+tig+4][nt*8+grp]) )
// ---------------------------------------------------------------------------
__global__ void k_bprep(const float* __restrict__ W1) {
    int idx = blockIdx.x * blockDim.x + threadIdx.x;
    if (idx >= 64 * 2 * 32) return;
    int lane  = idx & 31;
    int nt    = (idx >> 5) & 1;
    int kstep = idx >> 6;
    int grp = lane >> 2, tig = lane & 3;
    int k0 = kstep * 8 + tig;
    int n0 = nt * 8 + grp;
    unsigned u0, u1;
    float b0 = __ldg(W1 + k0 * HID + n0);
    float b1 = __ldg(W1 + (k0 + 4) * HID + n0);
    asm("cvt.rna.tf32.f32 %0, %1;" : "=r"(u0) : "f"(b0));
    asm("cvt.rna.tf32.f32 %0, %1;" : "=r"(u1) : "f"(b1));
    g_bfrag[idx] = make_float2(__uint_as_float(u0), __uint_as_float(u1));
}

// ---------------------------------------------------------------------------
// K1: g_xw16 = fp16(x @ W1) via tf32 mma.sync (m16n8k8).
//   296 blocks x 12 warps (2 blocks/SM, 24 warps/SM), one 32-row chunk per
//   warp. B frags prefetched from global (L2); x tiles via warp-private
//   3-stage cp.async pipeline, lookahead 2. No block barriers at all.
// ---------------------------------------------------------------------------
#define KT3     16
#define RPW3    32                          // rows per chunk
#define PADW3   20                          // floats per smem row
#define TILEF3  (RPW3 * PADW3)              // 640 floats / 2560 B per buffer
#define TPC3    (IN_DIM / KT3)              // 32 tiles per chunk
#define GW3     12                          // warps per block
#define STG3    3
#define GSM_B   (GW3 * STG3 * TILEF3 * 4)   // 92160 B

#define MMA_TF32(C, A, B0, B1)                                                \
    asm("mma.sync.aligned.m16n8k8.row.col.f32.tf32.tf32.f32 "                 \
        "{%0,%1,%2,%3}, {%4,%5,%6,%7}, {%8,%9}, {%0,%1,%2,%3};"               \
        : "+f"((C)[0]), "+f"((C)[1]), "+f"((C)[2]), "+f"((C)[3])              \
        : "r"((A)[0]), "r"((A)[1]), "r"((A)[2]), "r"((A)[3]),                 \
          "r"(B0), "r"(B1))

#define GLOAD3(J)                                                             \
    {                                                                         \
        int j_ = (J);                                                         \
        float* dst0 = sB + (j_ % STG3) * TILEF3;                              \
        _Pragma("unroll")                                                     \
        for (int i_ = 0; i_ < 4; ++i_) {                                      \
            int flat = i_ * 32 + lane;                                        \
            int r_ = flat >> 2, q_ = flat & 3;                                \
            unsigned d_ = (unsigned)__cvta_generic_to_shared(                 \
                dst0 + r_ * PADW3 + q_ * 4);                                  \
            long row_ = (long)wg * RPW3 + r_;                                 \
            int ok_ = (row_ < n);                                             \
            const float* s_ = x + (ok_ ? (row_ * IN_DIM                       \
                                          + j_ * KT3 + q_ * 4) : 0);          \
            int sz_ = ok_ ? 16 : 0;                                           \
            asm volatile("cp.async.cg.shared.global [%0], [%1], 16, %2;"      \
                         :: "r"(d_), "l"(s_), "r"(sz_));                      \
        }                                                                     \
        asm volatile("cp.async.commit_group;");                              \
    }

__global__ void __launch_bounds__(384) k_gemm1(
        const float* __restrict__ x, int n) {
    extern __shared__ float sm[];

    int t    = threadIdx.x;
    int w    = t >> 5;
    int lane = t & 31;
    int grp  = lane >> 2;
    int tig  = lane & 3;
    float* sB = sm + w * (STG3 * TILEF3);
    int wg    = blockIdx.x * GW3 + w;

    int nchunks = (n + RPW3 - 1) / RPW3;
    if (wg >= nchunks) return;

    GLOAD3(0);
    GLOAD3(1);

    float c[2][2][4];
#pragma unroll
    for (int mt = 0; mt < 2; ++mt)
#pragma unroll
        for (int nt = 0; nt < 2; ++nt)
#pragma unroll
            for (int q = 0; q < 4; ++q) c[mt][nt][q] = 0.f;

#pragma unroll 1
    for (int j = 0; j < TPC3; ++j) {
        // prefetch this tile's B fragments (L2 hit; awaited at use)
        float2 bf[2][2];
#pragma unroll
        for (int kk = 0; kk < 2; ++kk)
#pragma unroll
            for (int nt = 0; nt < 2; ++nt)
                bf[kk][nt] = __ldg(g_bfrag + ((j * 2 + kk) * 2 + nt) * 32 + lane);

        if (j + 2 < TPC3) {
            GLOAD3(j + 2);
            asm volatile("cp.async.wait_group 2;");
        } else {
            int r = TPC3 - 1 - j;
            if (r == 1) asm volatile("cp.async.wait_group 1;");
            else        asm volatile("cp.async.wait_group 0;");
        }
        __syncwarp();

        const float* sX = sB + (j % STG3) * TILEF3;
#pragma unroll
        for (int kk = 0; kk < 2; ++kk) {
            unsigned a[2][4];
#pragma unroll
            for (int mt = 0; mt < 2; ++mt) {
                int r0 = mt * 16 + grp;
                const float* p0 = sX + r0 * PADW3 + kk * 8 + tig;
                const float* p1 = p0 + 8 * PADW3;
                a[mt][0] = __float_as_uint(p0[0]);
                a[mt][1] = __float_as_uint(p1[0]);
                a[mt][2] = __float_as_uint(p0[4]);
                a[mt][3] = __float_as_uint(p1[4]);
            }
#pragma unroll
            for (int nt = 0; nt < 2; ++nt) {
                unsigned b0 = __float_as_uint(bf[kk][nt].x);
                unsigned b1 = __float_as_uint(bf[kk][nt].y);
                MMA_TF32(c[0][nt], a[0], b0, b1);
                MMA_TF32(c[1][nt], a[1], b0, b1);
            }
        }
    }

    // epilogue: fp16 store.  c[mt][nt]: rows mt*16+grp(+8), cols nt*8+2tig(+1)
    long rowb = (long)wg * RPW3;
#pragma unroll
    for (int mt = 0; mt < 2; ++mt) {
#pragma unroll
        for (int nt = 0; nt < 2; ++nt) {
            long r0 = rowb + mt * 16 + grp;
            int  cb = nt * 8 + 2 * tig;
            __half2 h0 = __floats2half2_rn(c[mt][nt][0], c[mt][nt][1]);
            __half2 h1 = __floats2half2_rn(c[mt][nt][2], c[mt][nt][3]);
            if (r0 < n)
                *(__half2*)(g_xw16 + r0 * HID + cb) = h0;
            if (r0 + 8 < n)
                *(__half2*)(g_xw16 + (r0 + 8) * HID + cb) = h1;
        }
    }
}

// ---------------------------------------------------------------------------
// K2: g_h[dst] += w * fp32(g_xw16[src])
//   4 threads/edge, uint2 fp16 gather (32B/edge), one red.v4 per thread
//   (64B/edge contiguous) -> 2 wavefronts/edge.  4-edge ILP.
// ---------------------------------------------------------------------------
__global__ void k_spmm1(const int*   __restrict__ src,
                        const int*   __restrict__ dst,
                        const float* __restrict__ w, int E, int quarter) {
    int t = blockIdx.x * blockDim.x + threadIdx.x;
    int i = t >> 2;
    if (i >= quarter) return;
    int part = t & 3;

    int  e[4];  bool hv[4];
#pragma unroll
    for (int j = 0; j < 4; ++j) {
        e[j]  = i + j * quarter;
        hv[j] = (e[j] < E);
        if (!hv[j]) e[j] = 0;
    }

    int s[4], d[4]; float ww[4];
#pragma unroll
    for (int j = 0; j < 4; ++j) {
        s[j]  = __ldg(src + e[j]);
        d[j]  = __ldg(dst + e[j]);
        ww[j] = __ldg(w   + e[j]);
    }

    uint2 v[4];
#pragma unroll
    for (int j = 0; j < 4; ++j)
        v[j] = __ldg(((const uint2*)g_xw16) + (((size_t)s[j]) << 2) + part);

#pragma unroll
    for (int j = 0; j < 4; ++j) {
        if (!hv[j]) continue;
        float2 f0 = __half22float2(*reinterpret_cast<__half2*>(&v[j].x));
        float2 f1 = __half22float2(*reinterpret_cast<__half2*>(&v[j].y));
        float we = ww[j];
        float* a = g_h + (((size_t)d[j]) << 4) + (part << 2);
        asm volatile("red.global.add.v4.f32 [%0], {%1, %2, %3, %4};"
                     :: "l"(a), "f"(f0.x * we), "f"(f0.y * we),
                        "f"(f1.x * we), "f"(f1.y * we) : "memory");
    }
}

// ---------------------------------------------------------------------------
// K3: g_h2 = relu(g_h + b1) @ W2 ; out init to b2
// ---------------------------------------------------------------------------
__global__ void k_layer2a(const float* __restrict__ b1,
                          const float* __restrict__ W2,
                          const float* __restrict__ b2,
                          float* __restrict__ out, int n) {
    int i = blockIdx.x * blockDim.x + threadIdx.x;
    if (i >= n) return;
    float acc = 0.f;
#pragma unroll
    for (int p = 0; p < 4; ++p) {
        float4 hv = ((const float4*)g_h)[(size_t)i * 4 + p];
        float4 bv = __ldg(((const float4*)b1) + p);
        float4 wv = __ldg(((const float4*)W2) + p);
        acc += fmaxf(hv.x + bv.x, 0.f) * wv.x
             + fmaxf(hv.y + bv.y, 0.f) * wv.y
             + fmaxf(hv.z + bv.z, 0.f) * wv.z
             + fmaxf(hv.w + bv.w, 0.f) * wv.w;
    }
    g_h2[i] = acc;
    out[i]  = __ldg(b2);
}

// ---------------------------------------------------------------------------
// K4: out[dst] += w * g_h2[src]   (scalar RED, 4-edge ILP)
// ---------------------------------------------------------------------------
__global__ void k_spmm2(const int*   __restrict__ src,
                        const int*   __restrict__ dst,
                        const float* __restrict__ w,
                        float* __restrict__ out, int E, int quarter) {
    int i = blockIdx.x * blockDim.x + threadIdx.x;
    if (i >= quarter) return;

    int  e[4];  bool hv[4];
#pragma unroll
    for (int j = 0; j < 4; ++j) {
        e[j]  = i + j * quarter;
        hv[j] = (e[j] < E);
        if (!hv[j]) e[j] = 0;
    }
    int s[4], d[4]; float ww[4];
#pragma unroll
    for (int j = 0; j < 4; ++j) {
        s[j]  = __ldg(src + e[j]);
        d[j]  = __ldg(dst + e[j]);
        ww[j] = __ldg(w   + e[j]);
    }
    float h[4];
#pragma unroll
    for (int j = 0; j < 4; ++j) h[j] = __ldg(g_h2 + s[j]);
#pragma unroll
    for (int j = 0; j < 4; ++j)
        if (hv[j]) atomicAdd(out + d[j], ww[j] * h[j]);
}

// ---------------------------------------------------------------------------
extern "C" void kernel_launch(void* const* d_in, const int* in_sizes, int n_in,
                              void* d_out, int out_size) {
    const float* x   = (const float*)d_in[0];
    const int*   src = (const int*)  d_in[1];
    const int*   dst = (const int*)  d_in[2];
    const float* w   = (const float*)d_in[3];
    const float* W1  = (const float*)d_in[4];
    const float* b1  = (const float*)d_in[5];
    const float* W2  = (const float*)d_in[6];
    const float* b2  = (const float*)d_in[7];
    float* out = (float*)d_out;

    int N = in_sizes[0] / IN_DIM;
    int E = in_sizes[1];

    const int T = 256;

    // slot 1: zero g_h
    int n4 = N * HID / 4;
    k_zero<<<(n4 + T - 1) / T, T>>>(n4);

    // slot 2: build B fragments
    k_bprep<<<(64 * 2 * 32 + T - 1) / T, T>>>(W1);

    // slot 3: tf32 tensor-core gemm (3-stage pipeline, no block barriers)
    cudaFuncSetAttribute(k_gemm1,
        cudaFuncAttributeMaxDynamicSharedMemorySize, GSM_B);
    const int GB = 296;
    k_gemm1<<<GB, 384, GSM_B>>>(x, N);

    // slot 4 (ncu-sampled): spmm1, 4 thr/edge, uint2 fp16 gather, 4-edge ILP
    int q1 = (E + 3) >> 2;
    long long t1 = (long long)q1 * 4;
    k_spmm1<<<(unsigned)((t1 + 511) / 512), 512>>>(src, dst, w, E, q1);

    // slot 5: h2 = relu(h + b1) @ W2 ; out = b2
    k_layer2a<<<(N + T - 1) / T, T>>>(b1, W2, b2, out, N);

    // slot 6: out += scatter(w * h2[src]) by dst
    k_spmm2<<<(q1 + 511) / 512, 512>>>(src, dst, w, out, E, q1);
}

// round 13
// speedup vs baseline: 1.2744x; 1.0265x over previous
#include <cuda_runtime.h>
#include <cuda_fp16.h>
#include <cstdint>

#define NMAX    100000
#define IN_DIM  512
#define HID     16

typedef unsigned long long ull;

// Scratch (allocation-free per harness rules): __device__ globals.
__device__ __half g_xw16[(size_t)NMAX * HID];  // x @ W1 (fp16)    [N,16]
__device__ float  g_h [(size_t)NMAX * HID];    // spmm accumulator [N,16]
__device__ float  g_h2[(size_t)NMAX];          // relu(h+b1) @ W2  [N]
__device__ float2 g_bfrag[64 * 2 * 32];        // tf32 B fragments

// ---------------------------------------------------------------------------
// K0: zero the spmm-1 accumulator
// ---------------------------------------------------------------------------
__global__ void k_zero(int n4) {
    int i = blockIdx.x * blockDim.x + threadIdx.x;
    if (i < n4) ((float4*)g_h)[i] = make_float4(0.f, 0.f, 0.f, 0.f);
}

// ---------------------------------------------------------------------------
// K0b: build tf32 B fragments from W1 (once per call; 32 KB, L2-resident)
// ---------------------------------------------------------------------------
__global__ void k_bprep(const float* __restrict__ W1) {
    int idx = blockIdx.x * blockDim.x + threadIdx.x;
    if (idx >= 64 * 2 * 32) return;
    int lane  = idx & 31;
    int nt    = (idx >> 5) & 1;
    int kstep = idx >> 6;
    int grp = lane >> 2, tig = lane & 3;
    int k0 = kstep * 8 + tig;
    int n0 = nt * 8 + grp;
    unsigned u0, u1;
    float b0 = __ldg(W1 + k0 * HID + n0);
    float b1 = __ldg(W1 + (k0 + 4) * HID + n0);
    asm("cvt.rna.tf32.f32 %0, %1;" : "=r"(u0) : "f"(b0));
    asm("cvt.rna.tf32.f32 %0, %1;" : "=r"(u1) : "f"(b1));
    g_bfrag[idx] = make_float2(__uint_as_float(u0), __uint_as_float(u1));
}

// ---------------------------------------------------------------------------
// K1: g_xw16 = fp16(x @ W1) via tf32 mma.sync (m16n8k8).
//   296 blocks x 12 warps, one 32-row chunk per warp, B frags from L2,
//   warp-private 3-stage cp.async pipeline (lookahead 2), no block barriers.
// ---------------------------------------------------------------------------
#define KT3     16
#define RPW3    32
#define PADW3   20
#define TILEF3  (RPW3 * PADW3)
#define TPC3    (IN_DIM / KT3)
#define GW3     12
#define STG3    3
#define GSM_B   (GW3 * STG3 * TILEF3 * 4)   // 92160 B

#define MMA_TF32(C, A, B0, B1)                                                \
    asm("mma.sync.aligned.m16n8k8.row.col.f32.tf32.tf32.f32 "                 \
        "{%0,%1,%2,%3}, {%4,%5,%6,%7}, {%8,%9}, {%0,%1,%2,%3};"               \
        : "+f"((C)[0]), "+f"((C)[1]), "+f"((C)[2]), "+f"((C)[3])              \
        : "r"((A)[0]), "r"((A)[1]), "r"((A)[2]), "r"((A)[3]),                 \
          "r"(B0), "r"(B1))

#define GLOAD3(J)                                                             \
    {                                                                         \
        int j_ = (J);                                                         \
        float* dst0 = sB + (j_ % STG3) * TILEF3;                              \
        _Pragma("unroll")                                                     \
        for (int i_ = 0; i_ < 4; ++i_) {                                      \
            int flat = i_ * 32 + lane;                                        \
            int r_ = flat >> 2, q_ = flat & 3;                                \
            unsigned d_ = (unsigned)__cvta_generic_to_shared(                 \
                dst0 + r_ * PADW3 + q_ * 4);                                  \
            long row_ = (long)wg * RPW3 + r_;                                 \
            int ok_ = (row_ < n);                                             \
            const float* s_ = x + (ok_ ? (row_ * IN_DIM                       \
                                          + j_ * KT3 + q_ * 4) : 0);          \
            int sz_ = ok_ ? 16 : 0;                                           \
            asm volatile("cp.async.cg.shared.global [%0], [%1], 16, %2;"      \
                         :: "r"(d_), "l"(s_), "r"(sz_));                      \
        }                                                                     \
        asm volatile("cp.async.commit_group;");                              \
    }

__global__ void __launch_bounds__(384) k_gemm1(
        const float* __restrict__ x, int n) {
    extern __shared__ float sm[];

    int t    = threadIdx.x;
    int w    = t >> 5;
    int lane = t & 31;
    int grp  = lane >> 2;
    int tig  = lane & 3;
    float* sB = sm + w * (STG3 * TILEF3);
    int wg    = blockIdx.x * GW3 + w;

    int nchunks = (n + RPW3 - 1) / RPW3;
    if (wg >= nchunks) return;

    GLOAD3(0);
    GLOAD3(1);

    float c[2][2][4];
#pragma unroll
    for (int mt = 0; mt < 2; ++mt)
#pragma unroll
        for (int nt = 0; nt < 2; ++nt)
#pragma unroll
            for (int q = 0; q < 4; ++q) c[mt][nt][q] = 0.f;

#pragma unroll 1
    for (int j = 0; j < TPC3; ++j) {
        float2 bf[2][2];
#pragma unroll
        for (int kk = 0; kk < 2; ++kk)
#pragma unroll
            for (int nt = 0; nt < 2; ++nt)
                bf[kk][nt] = __ldg(g_bfrag + ((j * 2 + kk) * 2 + nt) * 32 + lane);

        if (j + 2 < TPC3) {
            GLOAD3(j + 2);
            asm volatile("cp.async.wait_group 2;");
        } else {
            int r = TPC3 - 1 - j;
            if (r == 1) asm volatile("cp.async.wait_group 1;");
            else        asm volatile("cp.async.wait_group 0;");
        }
        __syncwarp();

        const float* sX = sB + (j % STG3) * TILEF3;
#pragma unroll
        for (int kk = 0; kk < 2; ++kk) {
            unsigned a[2][4];
#pragma unroll
            for (int mt = 0; mt < 2; ++mt) {
                int r0 = mt * 16 + grp;
                const float* p0 = sX + r0 * PADW3 + kk * 8 + tig;
                const float* p1 = p0 + 8 * PADW3;
                a[mt][0] = __float_as_uint(p0[0]);
                a[mt][1] = __float_as_uint(p1[0]);
                a[mt][2] = __float_as_uint(p0[4]);
                a[mt][3] = __float_as_uint(p1[4]);
            }
#pragma unroll
            for (int nt = 0; nt < 2; ++nt) {
                unsigned b0 = __float_as_uint(bf[kk][nt].x);
                unsigned b1 = __float_as_uint(bf[kk][nt].y);
                MMA_TF32(c[0][nt], a[0], b0, b1);
                MMA_TF32(c[1][nt], a[1], b0, b1);
            }
        }
    }

    long rowb = (long)wg * RPW3;
#pragma unroll
    for (int mt = 0; mt < 2; ++mt) {
#pragma unroll
        for (int nt = 0; nt < 2; ++nt) {
            long r0 = rowb + mt * 16 + grp;
            int  cb = nt * 8 + 2 * tig;
            __half2 h0 = __floats2half2_rn(c[mt][nt][0], c[mt][nt][1]);
            __half2 h1 = __floats2half2_rn(c[mt][nt][2], c[mt][nt][3]);
            if (r0 < n)
                *(__half2*)(g_xw16 + r0 * HID + cb) = h0;
            if (r0 + 8 < n)
                *(__half2*)(g_xw16 + (r0 + 8) * HID + cb) = h1;
        }
    }
}

// ---------------------------------------------------------------------------
// K2: g_h[dst] += w * fp32(g_xw16[src])
//   4 consecutive edges per thread-quad: metadata via int4/float4 (3 vector
//   loads replace 12 scalar), uint2 fp16 gather (1 wf/edge), red.v4 (1 wf/edge).
// ---------------------------------------------------------------------------
__global__ void k_spmm1(const int*   __restrict__ src,
                        const int*   __restrict__ dst,
                        const float* __restrict__ w, int E) {
    int t = blockIdx.x * blockDim.x + threadIdx.x;
    int i = t >> 2;                       // group of 4 consecutive edges
    int base = i << 2;
    if (base >= E) return;
    int part = t & 3;

    int4   s4, d4;
    float4 w4;
    if (base + 4 <= E) {
        s4 = __ldg((const int4*)  (src + base));
        d4 = __ldg((const int4*)  (dst + base));
        w4 = __ldg((const float4*)(w   + base));
    } else {                              // ragged tail (E%4 != 0)
        int   sv[4] = {0, 0, 0, 0}, dv[4] = {0, 0, 0, 0};
        float wv[4] = {0.f, 0.f, 0.f, 0.f};
        for (int j = 0; j < 4 && base + j < E; ++j) {
            sv[j] = __ldg(src + base + j);
            dv[j] = __ldg(dst + base + j);
            wv[j] = __ldg(w   + base + j);
        }
        s4 = make_int4(sv[0], sv[1], sv[2], sv[3]);
        d4 = make_int4(dv[0], dv[1], dv[2], dv[3]);
        w4 = make_float4(wv[0], wv[1], wv[2], wv[3]);
    }

    int   s[4] = {s4.x, s4.y, s4.z, s4.w};
    int   d[4] = {d4.x, d4.y, d4.z, d4.w};
    float ww[4] = {w4.x, w4.y, w4.z, w4.w};

    uint2 v[4];
#pragma unroll
    for (int j = 0; j < 4; ++j)
        v[j] = __ldg(((const uint2*)g_xw16) + (((size_t)s[j]) << 2) + part);

#pragma unroll
    for (int j = 0; j < 4; ++j) {
        if (base + j >= E) break;
        float2 f0 = __half22float2(*reinterpret_cast<__half2*>(&v[j].x));
        float2 f1 = __half22float2(*reinterpret_cast<__half2*>(&v[j].y));
        float we = ww[j];
        float* a = g_h + (((size_t)d[j]) << 4) + (part << 2);
        asm volatile("red.global.add.v4.f32 [%0], {%1, %2, %3, %4};"
                     :: "l"(a), "f"(f0.x * we), "f"(f0.y * we),
                        "f"(f1.x * we), "f"(f1.y * we) : "memory");
    }
}

// ---------------------------------------------------------------------------
// K3: g_h2 = relu(g_h + b1) @ W2 ; out init to b2
// ---------------------------------------------------------------------------
__global__ void k_layer2a(const float* __restrict__ b1,
                          const float* __restrict__ W2,
                          const float* __restrict__ b2,
                          float* __restrict__ out, int n) {
    int i = blockIdx.x * blockDim.x + threadIdx.x;
    if (i >= n) return;
    float acc = 0.f;
#pragma unroll
    for (int p = 0; p < 4; ++p) {
        float4 hv = ((const float4*)g_h)[(size_t)i * 4 + p];
        float4 bv = __ldg(((const float4*)b1) + p);
        float4 wv = __ldg(((const float4*)W2) + p);
        acc += fmaxf(hv.x + bv.x, 0.f) * wv.x
             + fmaxf(hv.y + bv.y, 0.f) * wv.y
             + fmaxf(hv.z + bv.z, 0.f) * wv.z
             + fmaxf(hv.w + bv.w, 0.f) * wv.w;
    }
    g_h2[i] = acc;
    out[i]  = __ldg(b2);
}

// ---------------------------------------------------------------------------
// K4: out[dst] += w * g_h2[src]
//   1 thread per 4 consecutive edges: int4/float4 metadata, scalar gathers,
//   scalar REDs.
// ---------------------------------------------------------------------------
__global__ void k_spmm2(const int*   __restrict__ src,
                        const int*   __restrict__ dst,
                        const float* __restrict__ w,
                        float* __restrict__ out, int E) {
    int i = blockIdx.x * blockDim.x + threadIdx.x;
    int base = i << 2;
    if (base >= E) return;

    int4   s4, d4;
    float4 w4;
    if (base + 4 <= E) {
        s4 = __ldg((const int4*)  (src + base));
        d4 = __ldg((const int4*)  (dst + base));
        w4 = __ldg((const float4*)(w   + base));
    } else {
        int   sv[4] = {0, 0, 0, 0}, dv[4] = {0, 0, 0, 0};
        float wv[4] = {0.f, 0.f, 0.f, 0.f};
        for (int j = 0; j < 4 && base + j < E; ++j) {
            sv[j] = __ldg(src + base + j);
            dv[j] = __ldg(dst + base + j);
            wv[j] = __ldg(w   + base + j);
        }
        s4 = make_int4(sv[0], sv[1], sv[2], sv[3]);
        d4 = make_int4(dv[0], dv[1], dv[2], dv[3]);
        w4 = make_float4(wv[0], wv[1], wv[2], wv[3]);
    }

    int   s[4] = {s4.x, s4.y, s4.z, s4.w};
    int   d[4] = {d4.x, d4.y, d4.z, d4.w};
    float ww[4] = {w4.x, w4.y, w4.z, w4.w};

    float h[4];
#pragma unroll
    for (int j = 0; j < 4; ++j) h[j] = __ldg(g_h2 + s[j]);

#pragma unroll
    for (int j = 0; j < 4; ++j) {
        if (base + j >= E) break;
        atomicAdd(out + d[j], ww[j] * h[j]);
    }
}

// ---------------------------------------------------------------------------
extern "C" void kernel_launch(void* const* d_in, const int* in_sizes, int n_in,
                              void* d_out, int out_size) {
    const float* x   = (const float*)d_in[0];
    const int*   src = (const int*)  d_in[1];
    const int*   dst = (const int*)  d_in[2];
    const float* w   = (const float*)d_in[3];
    const float* W1  = (const float*)d_in[4];
    const float* b1  = (const float*)d_in[5];
    const float* W2  = (const float*)d_in[6];
    const float* b2  = (const float*)d_in[7];
    float* out = (float*)d_out;

    int N = in_sizes[0] / IN_DIM;
    int E = in_sizes[1];

    const int T = 256;

    // slot 1: zero g_h
    int n4 = N * HID / 4;
    k_zero<<<(n4 + T - 1) / T, T>>>(n4);

    // slot 2: build B fragments
    k_bprep<<<(64 * 2 * 32 + T - 1) / T, T>>>(W1);

    // slot 3: tf32 tensor-core gemm
    cudaFuncSetAttribute(k_gemm1,
        cudaFuncAttributeMaxDynamicSharedMemorySize, GSM_B);
    const int GB = 296;
    k_gemm1<<<GB, 384, GSM_B>>>(x, N);

    // slot 4 (ncu-sampled): spmm1, consecutive-edge int4 metadata
    int ngroups = (E + 3) >> 2;
    long long t1 = (long long)ngroups * 4;
    k_spmm1<<<(unsigned)((t1 + 511) / 512), 512>>>(src, dst, w, E);

    // slot 5: h2 = relu(h + b1) @ W2 ; out = b2
    k_layer2a<<<(N + T - 1) / T, T>>>(b1, W2, b2, out, N);

    // slot 6: out += scatter(w * h2[src]) by dst
    k_spmm2<<<(ngroups + 511) / 512, 512>>>(src, dst, w, out, E);
}